// round 1
// baseline (speedup 1.0000x reference)
#include <cuda_runtime.h>
#include <math.h>

// Problem dims (fixed)
#define BB  64
#define NV  2048
#define NQ  512
#define HH  256
#define HA  128

// ---------------- scratch (device globals; no cudaMalloc allowed) ----------
__device__ float g_va[(size_t)BB * NV * HH];     // v @ Waff^T          128MB
__device__ float g_pv[(size_t)BB * NV * HA];     // v @ Wv^T + bv        64MB
__device__ float g_pq[(size_t)BB * NQ * HA];     // q @ Wq^T + bq        16MB
__device__ float g_aff[(size_t)BB * NQ * NV];    // tanh(q va^T)        256MB
__device__ float g_lv[BB * NV];                  // logits for a_v
__device__ float g_lq[BB * NQ];                  // logits for a_q

// ============================================================================
// Generic NT GEMM: C[M,N] = A[M,K] @ B[N,K]^T (+bias) (optional tanh)
// BM=BN=64, BK=16, 256 threads, 4x4 per thread. Optionally batched via z.
// ============================================================================
__global__ __launch_bounds__(256)
void gemm_nt_kernel(const float* __restrict__ A, const float* __restrict__ Bm,
                    const float* __restrict__ bias, float* __restrict__ C,
                    int M, int N, int K,
                    long sA, long sB, long sC, int doTanh)
{
    const int b = blockIdx.z;
    A  += (long)b * sA;
    Bm += (long)b * sB;
    C  += (long)b * sC;

    __shared__ float AsT[16][64];
    __shared__ float BsT[16][64];

    const int tid = threadIdx.x;
    const int tx = tid & 15, ty = tid >> 4;
    const int m0 = blockIdx.y * 64;
    const int n0 = blockIdx.x * 64;

    const int lr = tid >> 2;          // 0..63
    const int lk = (tid & 3) << 2;    // 0,4,8,12

    float acc[4][4] = {};

    for (int k0 = 0; k0 < K; k0 += 16) {
        float4 av = *(const float4*)&A [(long)(m0 + lr) * K + k0 + lk];
        float4 bv = *(const float4*)&Bm[(long)(n0 + lr) * K + k0 + lk];
        AsT[lk + 0][lr] = av.x; AsT[lk + 1][lr] = av.y;
        AsT[lk + 2][lr] = av.z; AsT[lk + 3][lr] = av.w;
        BsT[lk + 0][lr] = bv.x; BsT[lk + 1][lr] = bv.y;
        BsT[lk + 2][lr] = bv.z; BsT[lk + 3][lr] = bv.w;
        __syncthreads();
#pragma unroll
        for (int k = 0; k < 16; ++k) {
            const float4 a4 = *(const float4*)&AsT[k][ty << 2];
            const float4 b4 = *(const float4*)&BsT[k][tx << 2];
            float aw[4] = {a4.x, a4.y, a4.z, a4.w};
            float bw[4] = {b4.x, b4.y, b4.z, b4.w};
#pragma unroll
            for (int i = 0; i < 4; ++i)
#pragma unroll
                for (int j = 0; j < 4; ++j)
                    acc[i][j] = fmaf(aw[i], bw[j], acc[i][j]);
        }
        __syncthreads();
    }

    const int row = m0 + (ty << 2);
    const int col = n0 + (tx << 2);
#pragma unroll
    for (int i = 0; i < 4; ++i) {
        float4 o;
        float* po = &o.x;
#pragma unroll
        for (int j = 0; j < 4; ++j) {
            float v = acc[i][j];
            if (bias) v += bias[col + j];
            if (doTanh) v = tanhf(v);
            po[j] = v;
        }
        *(float4*)&C[(long)(row + i) * N + col] = o;
    }
}

// ============================================================================
// Fused hidden+logits kernel.
//   GEMM3 (A_ROW=false): T[n,a] = sum_q aff[b][q][n] * pq[b][q][a]
//       h = tanh(pv + T);  logit_v[n] = h . Whv + bhv
//   GEMM4 (A_ROW=true):  T[q,a] = sum_n aff[b][q][n] * pv[b][n][a]
//       h = tanh(pq + T);  logit_q[q] = h . Whq + bhq
// BM=64 (rows), BN=128 (= full HA), BK=16, 256 threads, 4x8 per thread.
// ============================================================================
template<bool A_ROW>
__global__ __launch_bounds__(256)
void hidden_logits_kernel(const float* __restrict__ aff,
                          const float* __restrict__ PB,    // [K, HA]
                          const float* __restrict__ PAdd,  // [M, HA]
                          const float* __restrict__ Wh,    // [HA]
                          const float* __restrict__ bh,    // [1]
                          float* __restrict__ logits,      // [M] per batch
                          int M, int K,
                          long sAff, long sPB, long sPAdd)
{
    const int b = blockIdx.z;
    aff    += (long)b * sAff;
    PB     += (long)b * sPB;
    PAdd   += (long)b * sPAdd;
    logits += (long)b * M;

    __shared__ float AsT[16][64];
    __shared__ float Bs [16][128];
    __shared__ float Padd[64][128];
    __shared__ float sWh[128];

    const int tid = threadIdx.x;
    const int tx = tid & 15, ty = tid >> 4;
    const int m0 = blockIdx.x * 64;

    // preload the additive tile and Wh
#pragma unroll
    for (int i = tid; i < 64 * 32; i += 256) {       // 2048 float4
        int r  = i >> 5;
        int c4 = (i & 31) << 2;
        *(float4*)&Padd[r][c4] = *(const float4*)&PAdd[(long)(m0 + r) * HA + c4];
    }
    if (tid < 128) sWh[tid] = Wh[tid];

    float acc[4][8] = {};

    for (int k0 = 0; k0 < K; k0 += 16) {
        // load A tile -> AsT[k][m]
        if (A_ROW) {
            const int m  = tid >> 2;
            const int kc = (tid & 3) << 2;
            float4 av = *(const float4*)&aff[(long)(m0 + m) * NV + k0 + kc];
            AsT[kc + 0][m] = av.x; AsT[kc + 1][m] = av.y;
            AsT[kc + 2][m] = av.z; AsT[kc + 3][m] = av.w;
        } else {
            const int k  = tid >> 4;
            const int m4 = (tid & 15) << 2;
            *(float4*)&AsT[k][m4] = *(const float4*)&aff[(long)(k0 + k) * NV + m0 + m4];
        }
        // load B tile -> Bs[k][a]
#pragma unroll
        for (int i = tid; i < 512; i += 256) {
            int k  = i >> 5;
            int c4 = (i & 31) << 2;
            *(float4*)&Bs[k][c4] = *(const float4*)&PB[(long)(k0 + k) * HA + c4];
        }
        __syncthreads();
#pragma unroll
        for (int k = 0; k < 16; ++k) {
            const float4 a4 = *(const float4*)&AsT[k][ty << 2];
            const float4 b0 = *(const float4*)&Bs[k][tx << 3];
            const float4 b1 = *(const float4*)&Bs[k][(tx << 3) + 4];
            float aw[4] = {a4.x, a4.y, a4.z, a4.w};
            float bw[8] = {b0.x, b0.y, b0.z, b0.w, b1.x, b1.y, b1.z, b1.w};
#pragma unroll
            for (int i = 0; i < 4; ++i)
#pragma unroll
                for (int j = 0; j < 8; ++j)
                    acc[i][j] = fmaf(aw[i], bw[j], acc[i][j]);
        }
        __syncthreads();
    }

    const float bhv = *bh;
#pragma unroll
    for (int i = 0; i < 4; ++i) {
        float partial = 0.f;
        const int r = (ty << 2) + i;
#pragma unroll
        for (int j = 0; j < 8; ++j) {
            const int a = (tx << 3) + j;
            float hval = tanhf(Padd[r][a] + acc[i][j]);
            partial = fmaf(sWh[a], hval, partial);
        }
        // reduce across the 16 tx lanes (half-warp)
#pragma unroll
        for (int off = 1; off < 16; off <<= 1)
            partial += __shfl_xor_sync(0xffffffffu, partial, off);
        if (tx == 0)
            logits[m0 + r] = partial + bhv;
    }
}

// ============================================================================
// Fused softmax (over sequence axis) + weighted sum of X rows -> out[b][H]
// One block per batch, 256 threads (= H).
// ============================================================================
__global__ __launch_bounds__(256)
void softmax_weighted_kernel(const float* __restrict__ logits,
                             const float* __restrict__ X,
                             float* __restrict__ out, int N)
{
    const int b = blockIdx.x;
    logits += (long)b * N;
    X      += (long)b * N * HH;

    __shared__ float sw[2048];
    __shared__ float red[256];

    const int tid = threadIdx.x;

    float mloc = -1e30f;
    for (int i = tid; i < N; i += 256) {
        float l = logits[i];
        sw[i] = l;
        mloc = fmaxf(mloc, l);
    }
    red[tid] = mloc;
    __syncthreads();
    for (int s = 128; s > 0; s >>= 1) {
        if (tid < s) red[tid] = fmaxf(red[tid], red[tid + s]);
        __syncthreads();
    }
    const float m = red[0];
    __syncthreads();

    float sloc = 0.f;
    for (int i = tid; i < N; i += 256) {
        float e = expf(sw[i] - m);
        sw[i] = e;
        sloc += e;
    }
    red[tid] = sloc;
    __syncthreads();
    for (int s = 128; s > 0; s >>= 1) {
        if (tid < s) red[tid] += red[tid + s];
        __syncthreads();
    }
    const float inv = 1.f / red[0];
    __syncthreads();

    // weighted sum over rows; thread tid handles column h = tid
    float acc = 0.f;
    const int h = tid;
#pragma unroll 4
    for (int n = 0; n < N; ++n)
        acc = fmaf(sw[n], X[(long)n * HH + h], acc);

    out[(long)b * HH + h] = acc * inv;
}

// ============================================================================
extern "C" void kernel_launch(void* const* d_in, const int* in_sizes, int n_in,
                              void* d_out, int out_size)
{
    const float* v    = (const float*)d_in[0];
    const float* q    = (const float*)d_in[1];
    const float* Waff = (const float*)d_in[2];
    const float* baff = (const float*)d_in[3];
    const float* Wv   = (const float*)d_in[4];
    const float* bv   = (const float*)d_in[5];
    const float* Wq   = (const float*)d_in[6];
    const float* bq   = (const float*)d_in[7];
    const float* Whv  = (const float*)d_in[8];
    const float* bhv  = (const float*)d_in[9];
    const float* Whq  = (const float*)d_in[10];
    const float* bhq  = (const float*)d_in[11];
    float* out = (float*)d_out;

    float *p_va, *p_pv, *p_pq, *p_aff, *p_lv, *p_lq;
    cudaGetSymbolAddress((void**)&p_va,  g_va);
    cudaGetSymbolAddress((void**)&p_pv,  g_pv);
    cudaGetSymbolAddress((void**)&p_pq,  g_pq);
    cudaGetSymbolAddress((void**)&p_aff, g_aff);
    cudaGetSymbolAddress((void**)&p_lv,  g_lv);
    cudaGetSymbolAddress((void**)&p_lq,  g_lq);

    // 1) va = v @ Waff^T + baff   [B*NV, H]
    gemm_nt_kernel<<<dim3(HH / 64, (BB * NV) / 64, 1), 256>>>(
        v, Waff, baff, p_va, BB * NV, HH, HH, 0, 0, 0, 0);

    // 2) pv = v @ Wv^T + bv       [B*NV, HA]
    gemm_nt_kernel<<<dim3(HA / 64, (BB * NV) / 64, 1), 256>>>(
        v, Wv, bv, p_pv, BB * NV, HA, HH, 0, 0, 0, 0);

    // 3) pq = q @ Wq^T + bq       [B*NQ, HA]
    gemm_nt_kernel<<<dim3(HA / 64, (BB * NQ) / 64, 1), 256>>>(
        q, Wq, bq, p_pq, BB * NQ, HA, HH, 0, 0, 0, 0);

    // 4) aff[b] = tanh(q[b] @ va[b]^T)   [NQ, NV] per batch
    gemm_nt_kernel<<<dim3(NV / 64, NQ / 64, BB), 256>>>(
        q, p_va, nullptr, p_aff, NQ, NV, HH,
        (long)NQ * HH, (long)NV * HH, (long)NQ * NV, 1);

    // 5) logits_v[b][n] = Whv . tanh(pv + aff^T @ pq) + bhv
    hidden_logits_kernel<false><<<dim3(NV / 64, 1, BB), 256>>>(
        p_aff, p_pq, p_pv, Whv, bhv, p_lv, NV, NQ,
        (long)NQ * NV, (long)NQ * HA, (long)NV * HA);

    // 6) logits_q[b][m] = Whq . tanh(pq + aff @ pv) + bhq
    hidden_logits_kernel<true><<<dim3(NQ / 64, 1, BB), 256>>>(
        p_aff, p_pv, p_pq, Whq, bhq, p_lq, NQ, NV,
        (long)NQ * NV, (long)NV * HA, (long)NQ * HA);

    // 7) v_hat = softmax(logits_v) . v   -> out[0 : B*H]
    softmax_weighted_kernel<<<BB, 256>>>(p_lv, v, out, NV);

    // 8) q_hat = softmax(logits_q) . q   -> out[B*H : 2*B*H]
    softmax_weighted_kernel<<<BB, 256>>>(p_lq, q, out + (long)BB * HH, NQ);
}

// round 2
// speedup vs baseline: 1.6494x; 1.6494x over previous
#include <cuda_runtime.h>
#include <math.h>

// Problem dims (fixed)
#define BB  64
#define NV  2048
#define NQ  512
#define HH  256
#define HA  128

// ---------------- scratch (device globals; no cudaMalloc allowed) ----------
__device__ float g_va[(size_t)BB * NV * HH];     // v @ Waff^T          128MB
__device__ float g_pv[(size_t)BB * NV * HA];     // v @ Wv^T + bv        64MB
__device__ float g_pq[(size_t)BB * NQ * HA];     // q @ Wq^T + bq        16MB
__device__ float g_aff[(size_t)BB * NQ * NV];    // tanh(q va^T)        256MB
__device__ float g_lv[BB * NV];                  // logits for a_v
__device__ float g_lq[BB * NQ];                  // logits for a_q

#define SMPAD 132   // 128 + 4 padding: kills staging-store bank conflicts

__device__ __forceinline__ float tanh_fast(float x) {
    // 1 - 2/(exp(2x)+1): 2 MUFU ops, abs err ~1e-6, saturates correctly at +-inf
    float e = __expf(2.0f * x);
    return 1.0f - __fdividef(2.0f, e + 1.0f);
}

// ============================================================================
// NT GEMM: C[M,N] = A[M,K] @ B[N,K]^T (+bias) (optional tanh)
// BM=BN=128, BK=16, 256 threads, 8x8 per thread, register-staged prefetch.
// M,N,K must be multiples of 128/128/16 (always true here).
// ============================================================================
template<int DO_TANH>
__global__ __launch_bounds__(256)
void gemm128_nt(const float* __restrict__ A, const float* __restrict__ Bm,
                const float* __restrict__ bias, float* __restrict__ C,
                int N, int K, long sA, long sB, long sC)
{
    const int b = blockIdx.z;
    A  += (long)b * sA;
    Bm += (long)b * sB;
    C  += (long)b * sC;

    __shared__ float As[16][SMPAD];
    __shared__ float Bs[16][SMPAD];

    const int tid = threadIdx.x;
    const int tx = tid & 15, ty = tid >> 4;
    const long m0 = (long)blockIdx.y * 128;
    const long n0 = (long)blockIdx.x * 128;

    const int lRow = tid >> 2;          // 0..63
    const int lCol = (tid & 3) << 2;    // 0,4,8,12

    const float* pA0 = A  + (m0 + lRow) * K + lCol;
    const float* pA1 = pA0 + (long)64 * K;
    const float* pB0 = Bm + (n0 + lRow) * K + lCol;
    const float* pB1 = pB0 + (long)64 * K;

    float4 ra0 = *(const float4*)pA0;
    float4 ra1 = *(const float4*)pA1;
    float4 rb0 = *(const float4*)pB0;
    float4 rb1 = *(const float4*)pB1;

    float acc[8][8] = {};

    for (int k0 = 0; k0 < K; k0 += 16) {
        // stage registers -> smem (transposed)
        As[lCol + 0][lRow]      = ra0.x; As[lCol + 1][lRow]      = ra0.y;
        As[lCol + 2][lRow]      = ra0.z; As[lCol + 3][lRow]      = ra0.w;
        As[lCol + 0][lRow + 64] = ra1.x; As[lCol + 1][lRow + 64] = ra1.y;
        As[lCol + 2][lRow + 64] = ra1.z; As[lCol + 3][lRow + 64] = ra1.w;
        Bs[lCol + 0][lRow]      = rb0.x; Bs[lCol + 1][lRow]      = rb0.y;
        Bs[lCol + 2][lRow]      = rb0.z; Bs[lCol + 3][lRow]      = rb0.w;
        Bs[lCol + 0][lRow + 64] = rb1.x; Bs[lCol + 1][lRow + 64] = rb1.y;
        Bs[lCol + 2][lRow + 64] = rb1.z; Bs[lCol + 3][lRow + 64] = rb1.w;
        __syncthreads();

        if (k0 + 16 < K) {
            ra0 = *(const float4*)(pA0 + k0 + 16);
            ra1 = *(const float4*)(pA1 + k0 + 16);
            rb0 = *(const float4*)(pB0 + k0 + 16);
            rb1 = *(const float4*)(pB1 + k0 + 16);
        }

#pragma unroll
        for (int k = 0; k < 16; ++k) {
            const float4 a0 = *(const float4*)&As[k][ty << 2];
            const float4 a1 = *(const float4*)&As[k][64 + (ty << 2)];
            const float4 b0 = *(const float4*)&Bs[k][tx << 2];
            const float4 b1 = *(const float4*)&Bs[k][64 + (tx << 2)];
            float aw[8] = {a0.x, a0.y, a0.z, a0.w, a1.x, a1.y, a1.z, a1.w};
            float bw[8] = {b0.x, b0.y, b0.z, b0.w, b1.x, b1.y, b1.z, b1.w};
#pragma unroll
            for (int i = 0; i < 8; ++i)
#pragma unroll
                for (int j = 0; j < 8; ++j)
                    acc[i][j] = fmaf(aw[i], bw[j], acc[i][j]);
        }
        __syncthreads();
    }

#pragma unroll
    for (int i = 0; i < 8; ++i) {
        const long r = m0 + (ty << 2) + (i & 3) + ((i >= 4) ? 64 : 0);
#pragma unroll
        for (int jh = 0; jh < 2; ++jh) {
            const long c = n0 + (tx << 2) + jh * 64;
            float4 o;
            float* po = &o.x;
#pragma unroll
            for (int j = 0; j < 4; ++j) {
                float val = acc[i][jh * 4 + j];
                if (bias) val += bias[c + j];
                if (DO_TANH) val = tanh_fast(val);
                po[j] = val;
            }
            *(float4*)&C[r * (long)N + c] = o;
        }
    }
}

// ============================================================================
// Fused hidden+logits kernel, 128x128 tiles, 8x8 per thread.
//   A_ROW=false: T[n,a] = sum_q aff[b][q][n] * PB[b][q][a]  (aff read col-wise,
//                which is contiguous since As[k][m] = aff[k][m] directly)
//   A_ROW=true:  T[q,a] = sum_n aff[b][q][n] * PB[b][n][a]  (transpose stage)
//   h = tanh(PAdd + T);  logits[m] = h . Wh + bh
// ============================================================================
template<bool A_ROW>
__global__ __launch_bounds__(256)
void hidden_logits128(const float* __restrict__ aff,
                      const float* __restrict__ PB,    // [K, HA]
                      const float* __restrict__ PAdd,  // [M, HA]
                      const float* __restrict__ Wh,    // [HA]
                      const float* __restrict__ bh,    // [1]
                      float* __restrict__ logits,      // [M] per batch
                      int M, int K, long sPB, long sPAdd)
{
    const int b = blockIdx.z;
    aff    += (long)b * ((long)NQ * NV);
    PB     += (long)b * sPB;
    PAdd   += (long)b * sPAdd;
    logits += (long)b * M;

    __shared__ float As[16][SMPAD];
    __shared__ float Bs[16][SMPAD];

    const int tid = threadIdx.x;
    const int tx = tid & 15, ty = tid >> 4;
    const long m0 = (long)blockIdx.x * 128;

    float acc[8][8] = {};

    // ---- prefetch pointers ----
    // B tile: Bs[k][a] = PB[(k0+k)*HA + a]; thread covers (kk, a4) and (kk+8, a4)
    const int kk = tid >> 5;            // 0..7
    const int a4 = (tid & 31) << 2;     // 0..124
    const float* pBq0 = PB + (long)kk * HA + a4;
    const float* pBq1 = pBq0 + 8 * HA;

    // A tile pointers
    const int lRow = tid >> 2;
    const int lCol = (tid & 3) << 2;
    const float* pAr0;  const float* pAr1;   // A_ROW=true (transpose stage)
    const float* pAc0;  const float* pAc1;   // A_ROW=false (direct stage)
    if (A_ROW) {
        pAr0 = aff + (m0 + lRow) * (long)NV + lCol;
        pAr1 = pAr0 + (long)64 * NV;
        pAc0 = pAc1 = nullptr;
    } else {
        pAc0 = aff + (long)kk * NV + m0 + a4;
        pAc1 = pAc0 + (long)8 * NV;
        pAr0 = pAr1 = nullptr;
    }

    float4 ra0, ra1;
    if (A_ROW) { ra0 = *(const float4*)pAr0; ra1 = *(const float4*)pAr1; }
    else       { ra0 = *(const float4*)pAc0; ra1 = *(const float4*)pAc1; }
    float4 rb0 = *(const float4*)pBq0;
    float4 rb1 = *(const float4*)pBq1;

    for (int k0 = 0; k0 < K; k0 += 16) {
        if (A_ROW) {
            As[lCol + 0][lRow]      = ra0.x; As[lCol + 1][lRow]      = ra0.y;
            As[lCol + 2][lRow]      = ra0.z; As[lCol + 3][lRow]      = ra0.w;
            As[lCol + 0][lRow + 64] = ra1.x; As[lCol + 1][lRow + 64] = ra1.y;
            As[lCol + 2][lRow + 64] = ra1.z; As[lCol + 3][lRow + 64] = ra1.w;
        } else {
            *(float4*)&As[kk][a4]     = ra0;
            *(float4*)&As[kk + 8][a4] = ra1;
        }
        *(float4*)&Bs[kk][a4]     = rb0;
        *(float4*)&Bs[kk + 8][a4] = rb1;
        __syncthreads();

        if (k0 + 16 < K) {
            if (A_ROW) {
                ra0 = *(const float4*)(pAr0 + k0 + 16);
                ra1 = *(const float4*)(pAr1 + k0 + 16);
            } else {
                ra0 = *(const float4*)(pAc0 + (long)(k0 + 16) * NV);
                ra1 = *(const float4*)(pAc1 + (long)(k0 + 16) * NV);
            }
            rb0 = *(const float4*)(pBq0 + (long)(k0 + 16) * HA);
            rb1 = *(const float4*)(pBq1 + (long)(k0 + 16) * HA);
        }

#pragma unroll
        for (int k = 0; k < 16; ++k) {
            const float4 a0 = *(const float4*)&As[k][ty << 2];
            const float4 a1 = *(const float4*)&As[k][64 + (ty << 2)];
            const float4 b0 = *(const float4*)&Bs[k][tx << 2];
            const float4 b1 = *(const float4*)&Bs[k][64 + (tx << 2)];
            float aw[8] = {a0.x, a0.y, a0.z, a0.w, a1.x, a1.y, a1.z, a1.w};
            float bw[8] = {b0.x, b0.y, b0.z, b0.w, b1.x, b1.y, b1.z, b1.w};
#pragma unroll
            for (int i = 0; i < 8; ++i)
#pragma unroll
                for (int j = 0; j < 8; ++j)
                    acc[i][j] = fmaf(aw[i], bw[j], acc[i][j]);
        }
        __syncthreads();
    }

    // ---- epilogue: tanh(PAdd + acc) . Wh, reduce over the 16 tx lanes ----
    const float bhv = *bh;
    float wh[8];
#pragma unroll
    for (int j = 0; j < 4; ++j) {
        wh[j]     = Wh[(tx << 2) + j];
        wh[4 + j] = Wh[64 + (tx << 2) + j];
    }

#pragma unroll
    for (int i = 0; i < 8; ++i) {
        const long r = (ty << 2) + (i & 3) + ((i >= 4) ? 64 : 0);
        const float4 p0 = *(const float4*)&PAdd[(m0 + r) * HA + (tx << 2)];
        const float4 p1 = *(const float4*)&PAdd[(m0 + r) * HA + 64 + (tx << 2)];
        const float pv8[8] = {p0.x, p0.y, p0.z, p0.w, p1.x, p1.y, p1.z, p1.w};
        float partial = 0.f;
#pragma unroll
        for (int j = 0; j < 8; ++j)
            partial = fmaf(wh[j], tanh_fast(pv8[j] + acc[i][j]), partial);
#pragma unroll
        for (int off = 1; off < 16; off <<= 1)
            partial += __shfl_xor_sync(0xffffffffu, partial, off);
        if (tx == 0)
            logits[m0 + r] = partial + bhv;
    }
}

// ============================================================================
// Fused softmax (over sequence axis) + weighted sum of X rows -> out[b][H]
// One block per batch, 256 threads (= H).
// ============================================================================
__global__ __launch_bounds__(256)
void softmax_weighted_kernel(const float* __restrict__ logits,
                             const float* __restrict__ X,
                             float* __restrict__ out, int N)
{
    const int b = blockIdx.x;
    logits += (long)b * N;
    X      += (long)b * N * HH;

    __shared__ float sw[2048];
    __shared__ float red[256];

    const int tid = threadIdx.x;

    float mloc = -1e30f;
    for (int i = tid; i < N; i += 256) {
        float l = logits[i];
        sw[i] = l;
        mloc = fmaxf(mloc, l);
    }
    red[tid] = mloc;
    __syncthreads();
    for (int s = 128; s > 0; s >>= 1) {
        if (tid < s) red[tid] = fmaxf(red[tid], red[tid + s]);
        __syncthreads();
    }
    const float m = red[0];
    __syncthreads();

    float sloc = 0.f;
    for (int i = tid; i < N; i += 256) {
        float e = expf(sw[i] - m);
        sw[i] = e;
        sloc += e;
    }
    red[tid] = sloc;
    __syncthreads();
    for (int s = 128; s > 0; s >>= 1) {
        if (tid < s) red[tid] += red[tid + s];
        __syncthreads();
    }
    const float inv = 1.f / red[0];
    __syncthreads();

    float acc = 0.f;
    const int h = tid;
#pragma unroll 4
    for (int n = 0; n < N; ++n)
        acc = fmaf(sw[n], X[(long)n * HH + h], acc);

    out[(long)b * HH + h] = acc * inv;
}

// ============================================================================
extern "C" void kernel_launch(void* const* d_in, const int* in_sizes, int n_in,
                              void* d_out, int out_size)
{
    const float* v    = (const float*)d_in[0];
    const float* q    = (const float*)d_in[1];
    const float* Waff = (const float*)d_in[2];
    const float* baff = (const float*)d_in[3];
    const float* Wv   = (const float*)d_in[4];
    const float* bv   = (const float*)d_in[5];
    const float* Wq   = (const float*)d_in[6];
    const float* bq   = (const float*)d_in[7];
    const float* Whv  = (const float*)d_in[8];
    const float* bhv  = (const float*)d_in[9];
    const float* Whq  = (const float*)d_in[10];
    const float* bhq  = (const float*)d_in[11];
    float* out = (float*)d_out;

    float *p_va, *p_pv, *p_pq, *p_aff, *p_lv, *p_lq;
    cudaGetSymbolAddress((void**)&p_va,  g_va);
    cudaGetSymbolAddress((void**)&p_pv,  g_pv);
    cudaGetSymbolAddress((void**)&p_pq,  g_pq);
    cudaGetSymbolAddress((void**)&p_aff, g_aff);
    cudaGetSymbolAddress((void**)&p_lv,  g_lv);
    cudaGetSymbolAddress((void**)&p_lq,  g_lq);

    // 1) va = v @ Waff^T + baff   [B*NV, H]
    gemm128_nt<0><<<dim3(HH / 128, (BB * NV) / 128, 1), 256>>>(
        v, Waff, baff, p_va, HH, HH, 0, 0, 0);

    // 2) pv = v @ Wv^T + bv       [B*NV, HA]
    gemm128_nt<0><<<dim3(HA / 128, (BB * NV) / 128, 1), 256>>>(
        v, Wv, bv, p_pv, HA, HH, 0, 0, 0);

    // 3) pq = q @ Wq^T + bq       [B*NQ, HA]
    gemm128_nt<0><<<dim3(HA / 128, (BB * NQ) / 128, 1), 256>>>(
        q, Wq, bq, p_pq, HA, HH, 0, 0, 0);

    // 4) aff[b] = tanh(q[b] @ va[b]^T)   [NQ, NV] per batch
    gemm128_nt<1><<<dim3(NV / 128, NQ / 128, BB), 256>>>(
        q, p_va, nullptr, p_aff, NV, HH,
        (long)NQ * HH, (long)NV * HH, (long)NQ * NV);

    // 5) logits_v[b][n] = Whv . tanh(pv + aff^T @ pq) + bhv
    hidden_logits128<false><<<dim3(NV / 128, 1, BB), 256>>>(
        p_aff, p_pq, p_pv, Whv, bhv, p_lv, NV, NQ,
        (long)NQ * HA, (long)NV * HA);

    // 6) logits_q[b][m] = Whq . tanh(pq + aff @ pv) + bhq
    hidden_logits128<true><<<dim3(NQ / 128, 1, BB), 256>>>(
        p_aff, p_pv, p_pq, Whq, bhq, p_lq, NQ, NV,
        (long)NV * HA, (long)NQ * HA);

    // 7) v_hat = softmax(logits_v) . v   -> out[0 : B*H]
    softmax_weighted_kernel<<<BB, 256>>>(p_lv, v, out, NV);

    // 8) q_hat = softmax(logits_q) . q   -> out[B*H : 2*B*H]
    softmax_weighted_kernel<<<BB, 256>>>(p_lq, q, out + (long)BB * HH, NQ);
}